// round 1
// baseline (speedup 1.0000x reference)
#include <cuda_runtime.h>
#include <math.h>

#define BATCH 64
#define CDIM  256
#define NPOS  1024
#define SLOTS 8
#define DDIM  256
#define NITER 3
#define LN_EPS 1e-5f
#define ATT_SCALE 0.0625f   // D^-0.5 = 256^-0.5

// ---------------- device scratch (no allocations allowed) ----------------
__device__ float g_xn[BATCH * NPOS * CDIM];        // layernormed, transposed x  [B*N, C]
__device__ float g_k [BATCH * NPOS * DDIM];        // [B*N, D]
__device__ float g_v [BATCH * NPOS * DDIM];        // [B*N, D]
__device__ float g_slots[BATCH * SLOTS * DDIM];    // [B*S, D]
__device__ float g_q    [BATCH * SLOTS * DDIM];    // [B*S, D]
__device__ float g_upd  [8 * BATCH * SLOTS * DDIM];// partial updates, 8 n-chunks

// ---------------- init slots: broadcast slots_mu over batch ----------------
__global__ void k_init_slots(const float* __restrict__ mu) {
    int i = blockIdx.x * 256 + threadIdx.x;         // 131072 threads
    g_slots[i] = mu[i & (SLOTS * DDIM - 1)];
}

// ---------------- transpose + input LayerNorm ----------------
// x: [B, C, N] -> g_xn: [B*N, C], LN over C per (b, n)
__global__ void k_ln_in(const float* __restrict__ x,
                        const float* __restrict__ gam,
                        const float* __restrict__ bet) {
    __shared__ float tile[CDIM][33];
    __shared__ float mu_s[32], rs_s[32];
    int b  = blockIdx.y;
    int n0 = blockIdx.x * 32;
    int tid = threadIdx.x;
    const float* xb = x + (size_t)b * CDIM * NPOS;

    // coalesced load: 32 consecutive n per c
    for (int i = tid; i < CDIM * 32; i += 256) {
        int c = i >> 5, n = i & 31;
        tile[c][n] = xb[c * NPOS + n0 + n];
    }
    __syncthreads();

    int warp = tid >> 5, lane = tid & 31;
    for (int col = warp; col < 32; col += 8) {
        float s = 0.f, s2 = 0.f;
        #pragma unroll
        for (int c = lane; c < CDIM; c += 32) {
            float v = tile[c][col];
            s += v; s2 += v * v;
        }
        #pragma unroll
        for (int o = 16; o; o >>= 1) {
            s  += __shfl_xor_sync(0xffffffffu, s,  o);
            s2 += __shfl_xor_sync(0xffffffffu, s2, o);
        }
        if (lane == 0) {
            float m   = s * (1.f / CDIM);
            float var = s2 * (1.f / CDIM) - m * m;
            mu_s[col] = m;
            rs_s[col] = rsqrtf(var + LN_EPS);
        }
    }
    __syncthreads();

    // write: thread owns channel c = tid, iterate n; coalesced over c
    float gg = gam[tid], bb = bet[tid];
    float* xo = g_xn + ((size_t)b * NPOS + n0) * CDIM;
    #pragma unroll 8
    for (int n = 0; n < 32; n++) {
        float v = (tile[tid][n] - mu_s[n]) * rs_s[n] * gg + bb;
        xo[n * CDIM + tid] = v;
    }
}

// ---------------- big GEMM: [k | v] = g_xn @ [wk; wv]^T ----------------
// M = 65536, K = 256, N = 512 (first 256 -> k, next 256 -> v)
__global__ void __launch_bounds__(256, 2)
k_gemm_kv(const float* __restrict__ wk, const float* __restrict__ wv) {
    __shared__ float As[8][128];
    __shared__ float Bs[8][128];
    int m0 = blockIdx.x * 128;
    int n0 = blockIdx.y * 128;
    const float* W   = (n0 < 256) ? (wk + n0 * CDIM) : (wv + (n0 - 256) * CDIM);
    float*       Out = (n0 < 256) ? g_k : g_v;
    int ncol0 = n0 & 255;

    int tid  = threadIdx.x;
    int lrow = tid >> 1;
    int lcol = (tid & 1) * 4;
    int tx = tid & 15, ty = tid >> 4;

    const float* Aptr = g_xn + (size_t)(m0 + lrow) * CDIM + lcol;
    const float* Bptr = W + lrow * CDIM + lcol;

    float acc[8][8];
    #pragma unroll
    for (int i = 0; i < 8; i++)
        #pragma unroll
        for (int j = 0; j < 8; j++) acc[i][j] = 0.f;

    for (int k0 = 0; k0 < CDIM; k0 += 8) {
        float4 av = *(const float4*)(Aptr + k0);
        float4 bv = *(const float4*)(Bptr + k0);
        __syncthreads();
        As[lcol + 0][lrow] = av.x; As[lcol + 1][lrow] = av.y;
        As[lcol + 2][lrow] = av.z; As[lcol + 3][lrow] = av.w;
        Bs[lcol + 0][lrow] = bv.x; Bs[lcol + 1][lrow] = bv.y;
        Bs[lcol + 2][lrow] = bv.z; Bs[lcol + 3][lrow] = bv.w;
        __syncthreads();
        #pragma unroll
        for (int kk = 0; kk < 8; kk++) {
            float ar[8], br[8];
            *(float4*)(ar)     = *(const float4*)&As[kk][ty * 8];
            *(float4*)(ar + 4) = *(const float4*)&As[kk][ty * 8 + 4];
            *(float4*)(br)     = *(const float4*)&Bs[kk][tx * 8];
            *(float4*)(br + 4) = *(const float4*)&Bs[kk][tx * 8 + 4];
            #pragma unroll
            for (int i = 0; i < 8; i++)
                #pragma unroll
                for (int j = 0; j < 8; j++)
                    acc[i][j] = fmaf(ar[i], br[j], acc[i][j]);
        }
    }

    #pragma unroll
    for (int i = 0; i < 8; i++) {
        float* orow = Out + (size_t)(m0 + ty * 8 + i) * DDIM + ncol0 + tx * 8;
        *(float4*)(orow)     = make_float4(acc[i][0], acc[i][1], acc[i][2], acc[i][3]);
        *(float4*)(orow + 4) = make_float4(acc[i][4], acc[i][5], acc[i][6], acc[i][7]);
    }
}

// ---------------- q projection: q = LN(slots) @ wq^T ----------------
__global__ void k_qproj(const float* __restrict__ lg, const float* __restrict__ lb,
                        const float* __restrict__ wq) {
    int b = blockIdx.x;
    __shared__ float sn[SLOTS][DDIM];
    int tid = threadIdx.x, warp = tid >> 5, lane = tid & 31;

    {   // LN: warp per slot row
        int s = warp;
        const float* row = g_slots + (size_t)(b * SLOTS + s) * DDIM;
        float v[8]; float sum = 0.f, sq = 0.f;
        #pragma unroll
        for (int j = 0; j < 8; j++) {
            v[j] = row[lane + 32 * j];
            sum += v[j]; sq += v[j] * v[j];
        }
        #pragma unroll
        for (int o = 16; o; o >>= 1) {
            sum += __shfl_xor_sync(0xffffffffu, sum, o);
            sq  += __shfl_xor_sync(0xffffffffu, sq,  o);
        }
        float m = sum * (1.f / DDIM);
        float r = rsqrtf(sq * (1.f / DDIM) - m * m + LN_EPS);
        #pragma unroll
        for (int j = 0; j < 8; j++) {
            int c = lane + 32 * j;
            sn[s][c] = (v[j] - m) * r * lg[c] + lb[c];
        }
    }
    __syncthreads();

    int d = tid;
    const float* w = wq + d * DDIM;
    float acc[SLOTS];
    #pragma unroll
    for (int s = 0; s < SLOTS; s++) acc[s] = 0.f;
    for (int c = 0; c < DDIM; c++) {
        float ww = w[c];
        #pragma unroll
        for (int s = 0; s < SLOTS; s++) acc[s] = fmaf(sn[s][c], ww, acc[s]);
    }
    #pragma unroll
    for (int s = 0; s < SLOTS; s++)
        g_q[(size_t)(b * SLOTS + s) * DDIM + d] = acc[s];
}

// ---------------- attention: logits, softmax over S, partial updates ----------------
__global__ void k_attn(float* __restrict__ attn_out) {
    int b = blockIdx.x, ch = blockIdx.y;
    int n0 = ch * 128;
    __shared__ float qs[SLOTS][DDIM];   // 8KB
    __shared__ float as_[128][SLOTS];   // 4KB
    int tid = threadIdx.x;

    for (int i = tid; i < SLOTS * DDIM; i += 256)
        qs[i >> 8][i & 255] = g_q[(size_t)b * SLOTS * DDIM + i];
    __syncthreads();

    int warp = tid >> 5, lane = tid & 31;
    for (int nn = warp; nn < 128; nn += 8) {
        int n = n0 + nn;
        const float* kr = g_k + (size_t)(b * NPOS + n) * DDIM;
        float p[SLOTS];
        #pragma unroll
        for (int s = 0; s < SLOTS; s++) p[s] = 0.f;
        #pragma unroll
        for (int j = 0; j < 8; j++) {
            int c = lane + 32 * j;
            float kv = kr[c];
            #pragma unroll
            for (int s = 0; s < SLOTS; s++) p[s] = fmaf(kv, qs[s][c], p[s]);
        }
        #pragma unroll
        for (int o = 16; o; o >>= 1)
            #pragma unroll
            for (int s = 0; s < SLOTS; s++)
                p[s] += __shfl_xor_sync(0xffffffffu, p[s], o);

        float mx = -1e30f;
        #pragma unroll
        for (int s = 0; s < SLOTS; s++) { p[s] *= ATT_SCALE; mx = fmaxf(mx, p[s]); }
        float ssum = 0.f;
        #pragma unroll
        for (int s = 0; s < SLOTS; s++) { p[s] = expf(p[s] - mx); ssum += p[s]; }
        float inv = 1.f / ssum;
        if (lane == 0) {
            #pragma unroll
            for (int s = 0; s < SLOTS; s++) {
                float a = p[s] * inv;
                as_[nn][s] = a;
                if (attn_out) attn_out[(size_t)(b * NPOS + n) * SLOTS + s] = a;
            }
        }
    }
    __syncthreads();

    // updates partial: thread owns channel c = tid
    int c = tid;
    float acc[SLOTS];
    #pragma unroll
    for (int s = 0; s < SLOTS; s++) acc[s] = 0.f;
    const float* vb = g_v + (size_t)(b * NPOS + n0) * DDIM + c;
    for (int nn = 0; nn < 128; nn++) {
        float vv = vb[(size_t)nn * DDIM];
        #pragma unroll
        for (int s = 0; s < SLOTS; s++) acc[s] = fmaf(as_[nn][s], vv, acc[s]);
    }
    float* up = g_upd + (size_t)((ch * BATCH + b) * SLOTS) * DDIM + c;
    #pragma unroll
    for (int s = 0; s < SLOTS; s++) up[(size_t)s * DDIM] = acc[s];
}

// ---------------- slot update: reduce partials + GRU + LN + MLP ----------------
__global__ void k_slot_update(const float* __restrict__ wih, const float* __restrict__ whh,
                              const float* __restrict__ bih, const float* __restrict__ bhh,
                              const float* __restrict__ lg,  const float* __restrict__ lb,
                              const float* __restrict__ w1,  const float* __restrict__ b1,
                              const float* __restrict__ w2,  const float* __restrict__ b2,
                              float* __restrict__ out_slots, int write_out) {
    int b = blockIdx.x, half = blockIdx.y;   // half: slots [half*4, half*4+4)
    __shared__ float u [4][DDIM];
    __shared__ float h [4][DDIM];
    __shared__ float nh[4][DDIM];
    __shared__ float hm[4][DDIM];
    int tid = threadIdx.x;
    int sbase = half * 4;

    for (int i = tid; i < 4 * DDIM; i += 256) {
        int s = i >> 8, c = i & 255;
        float a = 0.f;
        #pragma unroll
        for (int chn = 0; chn < 8; chn++)
            a += g_upd[(size_t)((chn * BATCH + b) * SLOTS + sbase + s) * DDIM + c];
        u[s][c] = a;
        h[s][c] = g_slots[(size_t)(b * SLOTS + sbase + s) * DDIM + c];
    }
    __syncthreads();

    // GRU: thread owns gate-dim d = tid
    int d = tid;
    float ir[4] = {0,0,0,0}, iz[4] = {0,0,0,0}, in_[4] = {0,0,0,0};
    float hr[4] = {0,0,0,0}, hz[4] = {0,0,0,0}, hn_[4] = {0,0,0,0};
    const float* wir = wih + (size_t)d * DDIM;
    const float* wiz = wih + (size_t)(DDIM + d) * DDIM;
    const float* win = wih + (size_t)(2 * DDIM + d) * DDIM;
    const float* whr = whh + (size_t)d * DDIM;
    const float* whz = whh + (size_t)(DDIM + d) * DDIM;
    const float* whn = whh + (size_t)(2 * DDIM + d) * DDIM;
    for (int c = 0; c < DDIM; c++) {
        float a0 = wir[c], a1 = wiz[c], a2 = win[c];
        float c0 = whr[c], c1 = whz[c], c2 = whn[c];
        #pragma unroll
        for (int s = 0; s < 4; s++) {
            float uu = u[s][c], hh = h[s][c];
            ir[s] = fmaf(a0, uu, ir[s]); iz[s] = fmaf(a1, uu, iz[s]); in_[s] = fmaf(a2, uu, in_[s]);
            hr[s] = fmaf(c0, hh, hr[s]); hz[s] = fmaf(c1, hh, hz[s]); hn_[s] = fmaf(c2, hh, hn_[s]);
        }
    }
    float bir = bih[d], biz = bih[DDIM + d], bin = bih[2 * DDIM + d];
    float bhr = bhh[d], bhz = bhh[DDIM + d], bhn = bhh[2 * DDIM + d];
    #pragma unroll
    for (int s = 0; s < 4; s++) {
        float r = 1.f / (1.f + expf(-(ir[s] + bir + hr[s] + bhr)));
        float z = 1.f / (1.f + expf(-(iz[s] + biz + hz[s] + bhz)));
        float n = tanhf(in_[s] + bin + r * (hn_[s] + bhn));
        nh[s][d] = (1.f - z) * n + z * h[s][d];
    }
    __syncthreads();

    // LN(nh) -> u (reuse)
    int warp = tid >> 5, lane = tid & 31;
    if (warp < 4) {
        int s = warp;
        float v[8]; float sum = 0.f, sq = 0.f;
        #pragma unroll
        for (int j = 0; j < 8; j++) {
            v[j] = nh[s][lane + 32 * j];
            sum += v[j]; sq += v[j] * v[j];
        }
        #pragma unroll
        for (int o = 16; o; o >>= 1) {
            sum += __shfl_xor_sync(0xffffffffu, sum, o);
            sq  += __shfl_xor_sync(0xffffffffu, sq,  o);
        }
        float m = sum * (1.f / DDIM);
        float rs = rsqrtf(sq * (1.f / DDIM) - m * m + LN_EPS);
        #pragma unroll
        for (int j = 0; j < 8; j++) {
            int c = lane + 32 * j;
            u[s][c] = (v[j] - m) * rs * lg[c] + lb[c];
        }
    }
    __syncthreads();

    // hmid = relu(LN @ w1^T + b1)
    float m4[4] = {0,0,0,0};
    const float* w1r = w1 + (size_t)d * DDIM;
    for (int c = 0; c < DDIM; c++) {
        float ww = w1r[c];
        #pragma unroll
        for (int s = 0; s < 4; s++) m4[s] = fmaf(u[s][c], ww, m4[s]);
    }
    float bb1 = b1[d];
    #pragma unroll
    for (int s = 0; s < 4; s++) hm[s][d] = fmaxf(m4[s] + bb1, 0.f);
    __syncthreads();

    // slots = nh + hmid @ w2^T + b2
    float o4[4] = {0,0,0,0};
    const float* w2r = w2 + (size_t)d * DDIM;
    for (int c = 0; c < DDIM; c++) {
        float ww = w2r[c];
        #pragma unroll
        for (int s = 0; s < 4; s++) o4[s] = fmaf(hm[s][c], ww, o4[s]);
    }
    float bb2 = b2[d];
    #pragma unroll
    for (int s = 0; s < 4; s++) {
        float res = nh[s][d] + o4[s] + bb2;
        g_slots[(size_t)(b * SLOTS + sbase + s) * DDIM + d] = res;
        if (write_out && out_slots)
            out_slots[(size_t)(b * SLOTS + sbase + s) * DDIM + d] = res;
    }
}

// ---------------- host launcher ----------------
extern "C" void kernel_launch(void* const* d_in, const int* in_sizes, int n_in,
                              void* d_out, int out_size) {
    const float* x        = (const float*)d_in[0];
    const float* slots_mu = (const float*)d_in[1];
    const float* ln_in_g  = (const float*)d_in[2];
    const float* ln_in_b  = (const float*)d_in[3];
    const float* wk       = (const float*)d_in[4];
    const float* wv       = (const float*)d_in[5];
    const float* ln_s_g   = (const float*)d_in[6];
    const float* ln_s_b   = (const float*)d_in[7];
    const float* wq       = (const float*)d_in[8];
    const float* gru_wih  = (const float*)d_in[9];
    const float* gru_whh  = (const float*)d_in[10];
    const float* gru_bih  = (const float*)d_in[11];
    const float* gru_bhh  = (const float*)d_in[12];
    const float* ln_m_g   = (const float*)d_in[13];
    const float* ln_m_b   = (const float*)d_in[14];
    const float* mlp_w1   = (const float*)d_in[15];
    const float* mlp_b1   = (const float*)d_in[16];
    const float* mlp_w2   = (const float*)d_in[17];
    const float* mlp_b2   = (const float*)d_in[18];

    float* out = (float*)d_out;
    float* out_slots = nullptr;
    float* out_attn  = nullptr;
    const int SLOTS_SZ = BATCH * SLOTS * DDIM;       // 131072
    const int ATTN_SZ  = BATCH * NPOS * SLOTS;       // 524288
    if (out_size >= SLOTS_SZ + ATTN_SZ) { out_slots = out; out_attn = out + SLOTS_SZ; }
    else if (out_size == ATTN_SZ)       { out_attn = out; }
    else                                { out_slots = out; }

    k_init_slots<<<512, 256>>>(slots_mu);
    k_ln_in<<<dim3(32, 64), 256>>>(x, ln_in_g, ln_in_b);
    k_gemm_kv<<<dim3(512, 4), 256>>>(wk, wv);

    for (int it = 0; it < NITER; it++) {
        k_qproj<<<64, 256>>>(ln_s_g, ln_s_b, wq);
        k_attn<<<dim3(64, 8), 256>>>((it == NITER - 1) ? out_attn : nullptr);
        k_slot_update<<<dim3(64, 2), 256>>>(gru_wih, gru_whh, gru_bih, gru_bhh,
                                            ln_m_g, ln_m_b, mlp_w1, mlp_b1,
                                            mlp_w2, mlp_b2,
                                            out_slots, (it == NITER - 1) ? 1 : 0);
    }
}

// round 3
// speedup vs baseline: 1.6276x; 1.6276x over previous
#include <cuda_runtime.h>
#include <cuda_bf16.h>
#include <math.h>

#define BATCH 64
#define CDIM  256
#define NPOS  1024
#define SLOTS 8
#define DDIM  256
#define NITER 3
#define LN_EPS 1e-5f
#define ATT_SCALE 0.0625f   // D^-0.5 = 256^-0.5

// ---------------- device scratch (no allocations allowed) ----------------
__device__ __nv_bfloat16 g_xh[BATCH * NPOS * CDIM];  // LN(x) hi  [B*N, C]
__device__ __nv_bfloat16 g_xl[BATCH * NPOS * CDIM];  // LN(x) lo  [B*N, C]
__device__ __nv_bfloat16 g_wcat[512 * 768];          // [n][ wh | wh | wl ]
__device__ float g_k [BATCH * NPOS * DDIM];          // [B*N, D]
__device__ float g_v [BATCH * NPOS * DDIM];          // [B*N, D]
__device__ float g_slots[BATCH * SLOTS * DDIM];      // [B*S, D]
__device__ float g_q    [BATCH * SLOTS * DDIM];      // [B*S, D]
__device__ float g_upd  [8 * BATCH * SLOTS * DDIM];  // partial updates, 8 n-chunks
// transposed weights [c][d]
__device__ float g_wqT [CDIM * DDIM];
__device__ float g_w1T [DDIM * DDIM];
__device__ float g_w2T [DDIM * DDIM];
__device__ float g_wihT[DDIM * 3 * DDIM];
__device__ float g_whhT[DDIM * 3 * DDIM];

// ---------------- init slots: broadcast slots_mu over batch ----------------
__global__ void k_init_slots(const float* __restrict__ mu) {
    int i = blockIdx.x * 256 + threadIdx.x;
    g_slots[i] = mu[i & (SLOTS * DDIM - 1)];
}

// ---------------- one-time weight prep ----------------
__global__ void k_prep_wcat(const float* __restrict__ wk, const float* __restrict__ wv) {
    int i = blockIdx.x * 256 + threadIdx.x;   // 512*256 = 131072
    int n = i >> 8, c = i & 255;
    float w = (n < 256) ? wk[i] : wv[i - 65536];
    __nv_bfloat16 hi = __float2bfloat16(w);
    float lo = w - __bfloat162float(hi);
    g_wcat[n * 768 + c]       = hi;
    g_wcat[n * 768 + 256 + c] = hi;
    g_wcat[n * 768 + 512 + c] = __float2bfloat16(lo);
}

__global__ void k_prep_wT(const float* __restrict__ wq, const float* __restrict__ wih,
                          const float* __restrict__ whh, const float* __restrict__ w1,
                          const float* __restrict__ w2) {
    int i = blockIdx.x * 256 + threadIdx.x;   // 589824 total
    if (i < 65536)       { int d = i >> 8,           c = i & 255; g_wqT[c * 256 + d] = wq[i]; }
    else if (i < 131072) { int j = i - 65536,  d = j >> 8, c = j & 255; g_w1T[c * 256 + d] = w1[j]; }
    else if (i < 196608) { int j = i - 131072, d = j >> 8, c = j & 255; g_w2T[c * 256 + d] = w2[j]; }
    else if (i < 393216) { int j = i - 196608, g = j >> 8, c = j & 255; g_wihT[c * 768 + g] = wih[j]; }
    else                 { int j = i - 393216, g = j >> 8, c = j & 255; g_whhT[c * 768 + g] = whh[j]; }
}

// ---------------- transpose + input LayerNorm -> bf16 hi/lo ----------------
__global__ void k_ln_in(const float* __restrict__ x,
                        const float* __restrict__ gam,
                        const float* __restrict__ bet) {
    __shared__ float tile[CDIM][33];
    __shared__ float mu_s[32], rs_s[32];
    int b  = blockIdx.y;
    int n0 = blockIdx.x * 32;
    int tid = threadIdx.x;
    const float* xb = x + (size_t)b * CDIM * NPOS;

    for (int i = tid; i < CDIM * 32; i += 256) {
        int c = i >> 5, n = i & 31;
        tile[c][n] = xb[c * NPOS + n0 + n];
    }
    __syncthreads();

    int warp = tid >> 5, lane = tid & 31;
    for (int col = warp; col < 32; col += 8) {
        float s = 0.f, s2 = 0.f;
        #pragma unroll
        for (int c = lane; c < CDIM; c += 32) {
            float v = tile[c][col];
            s += v; s2 += v * v;
        }
        #pragma unroll
        for (int o = 16; o; o >>= 1) {
            s  += __shfl_xor_sync(0xffffffffu, s,  o);
            s2 += __shfl_xor_sync(0xffffffffu, s2, o);
        }
        if (lane == 0) {
            float m   = s * (1.f / CDIM);
            float var = s2 * (1.f / CDIM) - m * m;
            mu_s[col] = m;
            rs_s[col] = rsqrtf(var + LN_EPS);
        }
    }
    __syncthreads();

    float gg = gam[tid], bb = bet[tid];
    size_t base = ((size_t)b * NPOS + n0) * CDIM + tid;
    #pragma unroll 8
    for (int n = 0; n < 32; n++) {
        float v = (tile[tid][n] - mu_s[n]) * rs_s[n] * gg + bb;
        __nv_bfloat16 hi = __float2bfloat16(v);
        float lo = v - __bfloat162float(hi);
        g_xh[base + (size_t)n * CDIM] = hi;
        g_xl[base + (size_t)n * CDIM] = __float2bfloat16(lo);
    }
}

// ---------------- big GEMM via bf16 mma: [k|v] = xn @ [wk;wv]^T (bf16x3) ----------------
// M = 65536, Neff = 512, Keff = 768
__global__ void __launch_bounds__(256) k_gemm_kv_mma() {
    __shared__ __nv_bfloat16 As[128][40];
    __shared__ __nv_bfloat16 Bs[128][40];
    int m0 = blockIdx.x * 128;
    int n0 = blockIdx.y * 128;
    int tid = threadIdx.x, lane = tid & 31, warp = tid >> 5;
    int wm = (warp & 3) * 32, wn = (warp >> 2) * 64;
    float* Out = (n0 < 256) ? g_k : g_v;
    int ncol0 = n0 & 255;

    float acc[2][8][4];
    #pragma unroll
    for (int i = 0; i < 2; i++)
        #pragma unroll
        for (int j = 0; j < 8; j++)
            #pragma unroll
            for (int q = 0; q < 4; q++) acc[i][j][q] = 0.f;

    // smem fill mapping: 2 threads per row, each thread covers element chunks
    // (tid&1)*8 and (tid&1)*8+16  -> 4 uint4 per 32-element row slice (FULL coverage)
    int lr = tid >> 1, lc = (tid & 1) * 8;

    for (int kt = 0; kt < 768; kt += 32) {
        const __nv_bfloat16* A_src;
        int kk;
        if (kt < 256)      { A_src = g_xh; kk = kt; }
        else if (kt < 512) { A_src = g_xl; kk = kt - 256; }
        else               { A_src = g_xh; kk = kt - 512; }
        uint4 av0 = *(const uint4*)(A_src + (size_t)(m0 + lr) * CDIM + kk + lc);
        uint4 av1 = *(const uint4*)(A_src + (size_t)(m0 + lr) * CDIM + kk + lc + 16);
        uint4 bv0 = *(const uint4*)(g_wcat + (size_t)(n0 + lr) * 768 + kt + lc);
        uint4 bv1 = *(const uint4*)(g_wcat + (size_t)(n0 + lr) * 768 + kt + lc + 16);
        __syncthreads();
        *(uint4*)&As[lr][lc]      = av0;
        *(uint4*)&As[lr][lc + 16] = av1;
        *(uint4*)&Bs[lr][lc]      = bv0;
        *(uint4*)&Bs[lr][lc + 16] = bv1;
        __syncthreads();

        #pragma unroll
        for (int k16 = 0; k16 < 32; k16 += 16) {
            unsigned a[2][4], b[8][2];
            int ar = wm + (lane >> 2);
            int ac = k16 + (lane & 3) * 2;
            #pragma unroll
            for (int im = 0; im < 2; im++) {
                int r = ar + im * 16;
                a[im][0] = *(const unsigned*)&As[r][ac];
                a[im][1] = *(const unsigned*)&As[r + 8][ac];
                a[im][2] = *(const unsigned*)&As[r][ac + 8];
                a[im][3] = *(const unsigned*)&As[r + 8][ac + 8];
            }
            int bn = wn + (lane >> 2);
            #pragma unroll
            for (int jn = 0; jn < 8; jn++) {
                b[jn][0] = *(const unsigned*)&Bs[bn + jn * 8][ac];
                b[jn][1] = *(const unsigned*)&Bs[bn + jn * 8][ac + 8];
            }
            #pragma unroll
            for (int im = 0; im < 2; im++)
                #pragma unroll
                for (int jn = 0; jn < 8; jn++) {
                    asm volatile(
                        "mma.sync.aligned.m16n8k16.row.col.f32.bf16.bf16.f32 "
                        "{%0,%1,%2,%3}, {%4,%5,%6,%7}, {%8,%9}, {%0,%1,%2,%3};\n"
                        : "+f"(acc[im][jn][0]), "+f"(acc[im][jn][1]),
                          "+f"(acc[im][jn][2]), "+f"(acc[im][jn][3])
                        : "r"(a[im][0]), "r"(a[im][1]), "r"(a[im][2]), "r"(a[im][3]),
                          "r"(b[jn][0]), "r"(b[jn][1]));
                }
        }
    }

    #pragma unroll
    for (int im = 0; im < 2; im++)
        #pragma unroll
        for (int jn = 0; jn < 8; jn++) {
            int row = m0 + wm + im * 16 + (lane >> 2);
            int col = ncol0 + wn + jn * 8 + (lane & 3) * 2;
            float* p = Out + (size_t)row * DDIM + col;
            *(float2*)p = make_float2(acc[im][jn][0], acc[im][jn][1]);
            *(float2*)(p + 8 * DDIM) = make_float2(acc[im][jn][2], acc[im][jn][3]);
        }
}

// ---------------- q projection: q = LN(slots) @ wq^T ----------------
__global__ void k_qproj(const float* __restrict__ lg, const float* __restrict__ lb) {
    int b = blockIdx.x;
    __shared__ float sn[SLOTS][DDIM];
    int tid = threadIdx.x, warp = tid >> 5, lane = tid & 31;

    {   // LN: warp per slot row
        int s = warp;
        const float* row = g_slots + (size_t)(b * SLOTS + s) * DDIM;
        float v[8]; float sum = 0.f, sq = 0.f;
        #pragma unroll
        for (int j = 0; j < 8; j++) {
            v[j] = row[lane + 32 * j];
            sum += v[j]; sq += v[j] * v[j];
        }
        #pragma unroll
        for (int o = 16; o; o >>= 1) {
            sum += __shfl_xor_sync(0xffffffffu, sum, o);
            sq  += __shfl_xor_sync(0xffffffffu, sq,  o);
        }
        float m = sum * (1.f / DDIM);
        float r = rsqrtf(sq * (1.f / DDIM) - m * m + LN_EPS);
        #pragma unroll
        for (int j = 0; j < 8; j++) {
            int c = lane + 32 * j;
            sn[s][c] = (v[j] - m) * r * lg[c] + lb[c];
        }
    }
    __syncthreads();

    int d = tid;
    float acc[SLOTS];
    #pragma unroll
    for (int s = 0; s < SLOTS; s++) acc[s] = 0.f;
    #pragma unroll 8
    for (int c = 0; c < DDIM; c++) {
        float ww = g_wqT[c * DDIM + d];          // coalesced
        #pragma unroll
        for (int s = 0; s < SLOTS; s++) acc[s] = fmaf(sn[s][c], ww, acc[s]);
    }
    #pragma unroll
    for (int s = 0; s < SLOTS; s++)
        g_q[(size_t)(b * SLOTS + s) * DDIM + d] = acc[s];
}

// ---------------- attention: logits, softmax over S, partial updates ----------------
__global__ void k_attn(float* __restrict__ attn_out) {
    int b = blockIdx.x, ch = blockIdx.y;
    int n0 = ch * 128;
    __shared__ float qs[SLOTS][DDIM];
    __shared__ float as_[128][SLOTS];
    int tid = threadIdx.x;

    for (int i = tid; i < SLOTS * DDIM; i += 256)
        qs[i >> 8][i & 255] = g_q[(size_t)b * SLOTS * DDIM + i];
    __syncthreads();

    int warp = tid >> 5, lane = tid & 31;
    for (int nn = warp; nn < 128; nn += 8) {
        int n = n0 + nn;
        const float* kr = g_k + (size_t)(b * NPOS + n) * DDIM;
        float p[SLOTS];
        #pragma unroll
        for (int s = 0; s < SLOTS; s++) p[s] = 0.f;
        #pragma unroll
        for (int j = 0; j < 8; j++) {
            int c = lane + 32 * j;
            float kv = kr[c];
            #pragma unroll
            for (int s = 0; s < SLOTS; s++) p[s] = fmaf(kv, qs[s][c], p[s]);
        }
        #pragma unroll
        for (int o = 16; o; o >>= 1)
            #pragma unroll
            for (int s = 0; s < SLOTS; s++)
                p[s] += __shfl_xor_sync(0xffffffffu, p[s], o);

        float mx = -1e30f;
        #pragma unroll
        for (int s = 0; s < SLOTS; s++) { p[s] *= ATT_SCALE; mx = fmaxf(mx, p[s]); }
        float ssum = 0.f;
        #pragma unroll
        for (int s = 0; s < SLOTS; s++) { p[s] = expf(p[s] - mx); ssum += p[s]; }
        float inv = 1.f / ssum;
        if (lane == 0) {
            #pragma unroll
            for (int s = 0; s < SLOTS; s++) {
                float a = p[s] * inv;
                as_[nn][s] = a;
                if (attn_out) attn_out[(size_t)(b * NPOS + n) * SLOTS + s] = a;
            }
        }
    }
    __syncthreads();

    int c = tid;
    float acc[SLOTS];
    #pragma unroll
    for (int s = 0; s < SLOTS; s++) acc[s] = 0.f;
    const float* vb = g_v + (size_t)(b * NPOS + n0) * DDIM + c;
    for (int nn = 0; nn < 128; nn++) {
        float vv = vb[(size_t)nn * DDIM];
        #pragma unroll
        for (int s = 0; s < SLOTS; s++) acc[s] = fmaf(as_[nn][s], vv, acc[s]);
    }
    float* up = g_upd + (size_t)((ch * BATCH + b) * SLOTS) * DDIM + c;
    #pragma unroll
    for (int s = 0; s < SLOTS; s++) up[(size_t)s * DDIM] = acc[s];
}

// ---------------- slot update: reduce partials + GRU + LN + MLP ----------------
__global__ void k_slot_update(const float* __restrict__ bih, const float* __restrict__ bhh,
                              const float* __restrict__ lg,  const float* __restrict__ lb,
                              const float* __restrict__ b1,  const float* __restrict__ b2,
                              float* __restrict__ out_slots, int write_out) {
    int b = blockIdx.x, half = blockIdx.y;
    __shared__ float u [4][DDIM];
    __shared__ float h [4][DDIM];
    __shared__ float nh[4][DDIM];
    __shared__ float hm[4][DDIM];
    int tid = threadIdx.x;
    int sbase = half * 4;

    for (int i = tid; i < 4 * DDIM; i += 256) {
        int s = i >> 8, c = i & 255;
        float a = 0.f;
        #pragma unroll
        for (int chn = 0; chn < 8; chn++)
            a += g_upd[(size_t)((chn * BATCH + b) * SLOTS + sbase + s) * DDIM + c];
        u[s][c] = a;
        h[s][c] = g_slots[(size_t)(b * SLOTS + sbase + s) * DDIM + c];
    }
    __syncthreads();

    int d = tid;
    float ir[4] = {0,0,0,0}, iz[4] = {0,0,0,0}, in_[4] = {0,0,0,0};
    float hr[4] = {0,0,0,0}, hz[4] = {0,0,0,0}, hn_[4] = {0,0,0,0};
    #pragma unroll 4
    for (int c = 0; c < DDIM; c++) {
        float a0 = g_wihT[c * 768 + d];          // coalesced
        float a1 = g_wihT[c * 768 + 256 + d];
        float a2 = g_wihT[c * 768 + 512 + d];
        float c0 = g_whhT[c * 768 + d];
        float c1 = g_whhT[c * 768 + 256 + d];
        float c2 = g_whhT[c * 768 + 512 + d];
        #pragma unroll
        for (int s = 0; s < 4; s++) {
            float uu = u[s][c], hh = h[s][c];
            ir[s] = fmaf(a0, uu, ir[s]); iz[s] = fmaf(a1, uu, iz[s]); in_[s] = fmaf(a2, uu, in_[s]);
            hr[s] = fmaf(c0, hh, hr[s]); hz[s] = fmaf(c1, hh, hz[s]); hn_[s] = fmaf(c2, hh, hn_[s]);
        }
    }
    float bir = bih[d], biz = bih[DDIM + d], bin = bih[2 * DDIM + d];
    float bhr = bhh[d], bhz = bhh[DDIM + d], bhn = bhh[2 * DDIM + d];
    #pragma unroll
    for (int s = 0; s < 4; s++) {
        float r = 1.f / (1.f + expf(-(ir[s] + bir + hr[s] + bhr)));
        float z = 1.f / (1.f + expf(-(iz[s] + biz + hz[s] + bhz)));
        float n = tanhf(in_[s] + bin + r * (hn_[s] + bhn));
        nh[s][d] = (1.f - z) * n + z * h[s][d];
    }
    __syncthreads();

    int warp = tid >> 5, lane = tid & 31;
    if (warp < 4) {
        int s = warp;
        float v[8]; float sum = 0.f, sq = 0.f;
        #pragma unroll
        for (int j = 0; j < 8; j++) {
            v[j] = nh[s][lane + 32 * j];
            sum += v[j]; sq += v[j] * v[j];
        }
        #pragma unroll
        for (int o = 16; o; o >>= 1) {
            sum += __shfl_xor_sync(0xffffffffu, sum, o);
            sq  += __shfl_xor_sync(0xffffffffu, sq,  o);
        }
        float m = sum * (1.f / DDIM);
        float rs = rsqrtf(sq * (1.f / DDIM) - m * m + LN_EPS);
        #pragma unroll
        for (int j = 0; j < 8; j++) {
            int c = lane + 32 * j;
            u[s][c] = (v[j] - m) * rs * lg[c] + lb[c];
        }
    }
    __syncthreads();

    float m4[4] = {0,0,0,0};
    #pragma unroll 4
    for (int c = 0; c < DDIM; c++) {
        float ww = g_w1T[c * DDIM + d];          // coalesced
        #pragma unroll
        for (int s = 0; s < 4; s++) m4[s] = fmaf(u[s][c], ww, m4[s]);
    }
    float bb1 = b1[d];
    #pragma unroll
    for (int s = 0; s < 4; s++) hm[s][d] = fmaxf(m4[s] + bb1, 0.f);
    __syncthreads();

    float o4[4] = {0,0,0,0};
    #pragma unroll 4
    for (int c = 0; c < DDIM; c++) {
        float ww = g_w2T[c * DDIM + d];          // coalesced
        #pragma unroll
        for (int s = 0; s < 4; s++) o4[s] = fmaf(hm[s][c], ww, o4[s]);
    }
    float bb2 = b2[d];
    #pragma unroll
    for (int s = 0; s < 4; s++) {
        float res = nh[s][d] + o4[s] + bb2;
        g_slots[(size_t)(b * SLOTS + sbase + s) * DDIM + d] = res;
        if (write_out && out_slots)
            out_slots[(size_t)(b * SLOTS + sbase + s) * DDIM + d] = res;
    }
}

// ---------------- host launcher ----------------
extern "C" void kernel_launch(void* const* d_in, const int* in_sizes, int n_in,
                              void* d_out, int out_size) {
    const float* x        = (const float*)d_in[0];
    const float* slots_mu = (const float*)d_in[1];
    const float* ln_in_g  = (const float*)d_in[2];
    const float* ln_in_b  = (const float*)d_in[3];
    const float* wk       = (const float*)d_in[4];
    const float* wv       = (const float*)d_in[5];
    const float* ln_s_g   = (const float*)d_in[6];
    const float* ln_s_b   = (const float*)d_in[7];
    const float* wq       = (const float*)d_in[8];
    const float* gru_wih  = (const float*)d_in[9];
    const float* gru_whh  = (const float*)d_in[10];
    const float* gru_bih  = (const float*)d_in[11];
    const float* gru_bhh  = (const float*)d_in[12];
    const float* ln_m_g   = (const float*)d_in[13];
    const float* ln_m_b   = (const float*)d_in[14];
    const float* mlp_w1   = (const float*)d_in[15];
    const float* mlp_b1   = (const float*)d_in[16];
    const float* mlp_w2   = (const float*)d_in[17];
    const float* mlp_b2   = (const float*)d_in[18];

    float* out = (float*)d_out;
    float* out_slots = nullptr;
    float* out_attn  = nullptr;
    const int SLOTS_SZ = BATCH * SLOTS * DDIM;
    const int ATTN_SZ  = BATCH * NPOS * SLOTS;
    if (out_size >= SLOTS_SZ + ATTN_SZ) { out_slots = out; out_attn = out + SLOTS_SZ; }
    else if (out_size == ATTN_SZ)       { out_attn = out; }
    else                                { out_slots = out; }

    k_init_slots<<<512, 256>>>(slots_mu);
    k_prep_wcat<<<512, 256>>>(wk, wv);
    k_prep_wT<<<2304, 256>>>(wq, gru_wih, gru_whh, mlp_w1, mlp_w2);
    k_ln_in<<<dim3(32, 64), 256>>>(x, ln_in_g, ln_in_b);
    k_gemm_kv_mma<<<dim3(512, 4), 256>>>();

    for (int it = 0; it < NITER; it++) {
        k_qproj<<<64, 256>>>(ln_s_g, ln_s_b);
        k_attn<<<dim3(64, 8), 256>>>((it == NITER - 1) ? out_attn : nullptr);
        k_slot_update<<<dim3(64, 2), 256>>>(gru_bih, gru_bhh,
                                            ln_m_g, ln_m_b, mlp_b1, mlp_b2,
                                            out_slots, (it == NITER - 1) ? 1 : 0);
    }
}

// round 4
// speedup vs baseline: 1.7091x; 1.0501x over previous
#include <cuda_runtime.h>
#include <cuda_bf16.h>
#include <math.h>

#define BATCH 64
#define CDIM  256
#define NPOS  1024
#define SLOTS 8
#define DDIM  256
#define NITER 3
#define LN_EPS 1e-5f
#define ATT_SCALE 0.0625f   // D^-0.5 = 256^-0.5

// ---------------- device scratch (no allocations allowed) ----------------
__device__ __nv_bfloat16 g_xh[BATCH * NPOS * CDIM];  // LN(x) hi  [B*N, C]
__device__ __nv_bfloat16 g_xl[BATCH * NPOS * CDIM];  // LN(x) lo  [B*N, C]
__device__ __nv_bfloat16 g_wcat[512 * 768];          // [n][ wh | wh | wl ]
__device__ float g_k [BATCH * NPOS * DDIM];          // [B*N, D]
__device__ float g_v [BATCH * NPOS * DDIM];          // [B*N, D]
__device__ float g_slots[BATCH * SLOTS * DDIM];      // [B*S, D]
__device__ float g_upd  [8 * BATCH * SLOTS * DDIM];  // partial updates, 8 n-chunks
// transposed weights [c][d]
__device__ float g_wqT [CDIM * DDIM];
__device__ float g_w1T [DDIM * DDIM];
__device__ float g_w2T [DDIM * DDIM];
__device__ float g_wihT[DDIM * 3 * DDIM];
__device__ float g_whhT[DDIM * 3 * DDIM];

// ---------------- cp.async helpers ----------------
__device__ __forceinline__ void cp16(void* s, const void* g) {
    unsigned sa = (unsigned)__cvta_generic_to_shared(s);
    asm volatile("cp.async.cg.shared.global [%0], [%1], 16;\n" :: "r"(sa), "l"(g));
}
__device__ __forceinline__ void cp_commit() { asm volatile("cp.async.commit_group;\n"); }
template<int N> __device__ __forceinline__ void cp_wait() {
    asm volatile("cp.async.wait_group %0;\n" :: "n"(N));
}

// ---------------- one-time prep: slots init + wcat + transposed weights ----------------
__global__ void k_prep(const float* __restrict__ mu,
                       const float* __restrict__ wk, const float* __restrict__ wv,
                       const float* __restrict__ wq, const float* __restrict__ wih,
                       const float* __restrict__ whh, const float* __restrict__ w1,
                       const float* __restrict__ w2) {
    int i = blockIdx.x * 256 + threadIdx.x;   // grid covers 589824
    if (i < 131072) {
        g_slots[i] = mu[i & (SLOTS * DDIM - 1)];
        int n = i >> 8, c = i & 255;
        float w = (n < 256) ? wk[i] : wv[i - 65536];
        __nv_bfloat16 hi = __float2bfloat16(w);
        float lo = w - __bfloat162float(hi);
        g_wcat[n * 768 + c]       = hi;
        g_wcat[n * 768 + 256 + c] = hi;
        g_wcat[n * 768 + 512 + c] = __float2bfloat16(lo);
    }
    if (i < 65536) {
        int d = i >> 8, c = i & 255;
        g_wqT[c * 256 + d] = wq[i];
    } else if (i < 131072) {
        int j = i - 65536; int d = j >> 8; int c = j & 255;
        g_w1T[c * 256 + d] = w1[j];
    } else if (i < 196608) {
        int j = i - 131072; int d = j >> 8; int c = j & 255;
        g_w2T[c * 256 + d] = w2[j];
    } else if (i < 393216) {
        int j = i - 196608; int g = j >> 8; int c = j & 255;
        g_wihT[c * 768 + g] = wih[j];
    } else if (i < 589824) {
        int j = i - 393216; int g = j >> 8; int c = j & 255;
        g_whhT[c * 768 + g] = whh[j];
    }
}

// ---------------- transpose + input LayerNorm -> bf16 hi/lo ----------------
__global__ void k_ln_in(const float* __restrict__ x,
                        const float* __restrict__ gam,
                        const float* __restrict__ bet) {
    __shared__ float tile[CDIM][33];
    __shared__ float mu_s[32], rs_s[32];
    int b  = blockIdx.y;
    int n0 = blockIdx.x * 32;
    int tid = threadIdx.x;
    const float* xb = x + (size_t)b * CDIM * NPOS;

    for (int i = tid; i < CDIM * 32; i += 256) {
        int c = i >> 5, n = i & 31;
        tile[c][n] = xb[c * NPOS + n0 + n];
    }
    __syncthreads();

    int warp = tid >> 5, lane = tid & 31;
    for (int col = warp; col < 32; col += 8) {
        float s = 0.f, s2 = 0.f;
        #pragma unroll
        for (int c = lane; c < CDIM; c += 32) {
            float v = tile[c][col];
            s += v; s2 += v * v;
        }
        #pragma unroll
        for (int o = 16; o; o >>= 1) {
            s  += __shfl_xor_sync(0xffffffffu, s,  o);
            s2 += __shfl_xor_sync(0xffffffffu, s2, o);
        }
        if (lane == 0) {
            float m   = s * (1.f / CDIM);
            float var = s2 * (1.f / CDIM) - m * m;
            mu_s[col] = m;
            rs_s[col] = rsqrtf(var + LN_EPS);
        }
    }
    __syncthreads();

    float gg = gam[tid], bb = bet[tid];
    size_t base = ((size_t)b * NPOS + n0) * CDIM + tid;
    #pragma unroll 8
    for (int n = 0; n < 32; n++) {
        float v = (tile[tid][n] - mu_s[n]) * rs_s[n] * gg + bb;
        __nv_bfloat16 hi = __float2bfloat16(v);
        float lo = v - __bfloat162float(hi);
        g_xh[base + (size_t)n * CDIM] = hi;
        g_xl[base + (size_t)n * CDIM] = __float2bfloat16(lo);
    }
}

// ---------------- big GEMM via bf16 mma, 2-stage cp.async pipeline ----------------
// M = 65536, Neff = 512, Keff = 768
__global__ void __launch_bounds__(256, 2) k_gemm_kv_mma() {
    __shared__ __nv_bfloat16 As[2][128][40];
    __shared__ __nv_bfloat16 Bs[2][128][40];
    int m0 = blockIdx.x * 128;
    int n0 = blockIdx.y * 128;
    int tid = threadIdx.x, lane = tid & 31, warp = tid >> 5;
    int wm = (warp & 3) * 32, wn = (warp >> 2) * 64;
    float* Out = (n0 < 256) ? g_k : g_v;
    int ncol0 = n0 & 255;
    int lr = tid >> 1, lc = (tid & 1) * 8;

    float acc[2][8][4];
    #pragma unroll
    for (int i = 0; i < 2; i++)
        #pragma unroll
        for (int j = 0; j < 8; j++)
            #pragma unroll
            for (int q = 0; q < 4; q++) acc[i][j][q] = 0.f;

    auto issue = [&](int kti, int buf) {
        int kt = kti * 32;
        const __nv_bfloat16* A_src;
        int kk;
        if (kt < 256)      { A_src = g_xh; kk = kt; }
        else if (kt < 512) { A_src = g_xl; kk = kt - 256; }
        else               { A_src = g_xh; kk = kt - 512; }
        const __nv_bfloat16* ga = A_src + (size_t)(m0 + lr) * CDIM + kk + lc;
        const __nv_bfloat16* gb = g_wcat + (size_t)(n0 + lr) * 768 + kt + lc;
        cp16(&As[buf][lr][lc],      ga);
        cp16(&As[buf][lr][lc + 16], ga + 16);
        cp16(&Bs[buf][lr][lc],      gb);
        cp16(&Bs[buf][lr][lc + 16], gb + 16);
    };

    issue(0, 0); cp_commit();

    for (int i = 0; i < 24; i++) {
        int buf = i & 1;
        if (i < 23) { issue(i + 1, buf ^ 1); cp_commit(); cp_wait<1>(); }
        else        { cp_wait<0>(); }
        __syncthreads();

        #pragma unroll
        for (int k16 = 0; k16 < 32; k16 += 16) {
            unsigned a[2][4], b[8][2];
            int ar = wm + (lane >> 2);
            int ac = k16 + (lane & 3) * 2;
            #pragma unroll
            for (int im = 0; im < 2; im++) {
                int r = ar + im * 16;
                a[im][0] = *(const unsigned*)&As[buf][r][ac];
                a[im][1] = *(const unsigned*)&As[buf][r + 8][ac];
                a[im][2] = *(const unsigned*)&As[buf][r][ac + 8];
                a[im][3] = *(const unsigned*)&As[buf][r + 8][ac + 8];
            }
            int bn = wn + (lane >> 2);
            #pragma unroll
            for (int jn = 0; jn < 8; jn++) {
                b[jn][0] = *(const unsigned*)&Bs[buf][bn + jn * 8][ac];
                b[jn][1] = *(const unsigned*)&Bs[buf][bn + jn * 8][ac + 8];
            }
            #pragma unroll
            for (int im = 0; im < 2; im++)
                #pragma unroll
                for (int jn = 0; jn < 8; jn++) {
                    asm volatile(
                        "mma.sync.aligned.m16n8k16.row.col.f32.bf16.bf16.f32 "
                        "{%0,%1,%2,%3}, {%4,%5,%6,%7}, {%8,%9}, {%0,%1,%2,%3};\n"
                        : "+f"(acc[im][jn][0]), "+f"(acc[im][jn][1]),
                          "+f"(acc[im][jn][2]), "+f"(acc[im][jn][3])
                        : "r"(a[im][0]), "r"(a[im][1]), "r"(a[im][2]), "r"(a[im][3]),
                          "r"(b[jn][0]), "r"(b[jn][1]));
                }
        }
        __syncthreads();
    }

    #pragma unroll
    for (int im = 0; im < 2; im++)
        #pragma unroll
        for (int jn = 0; jn < 8; jn++) {
            int row = m0 + wm + im * 16 + (lane >> 2);
            int col = ncol0 + wn + jn * 8 + (lane & 3) * 2;
            float* p = Out + (size_t)row * DDIM + col;
            *(float2*)p = make_float2(acc[im][jn][0], acc[im][jn][1]);
            *(float2*)(p + 8 * DDIM) = make_float2(acc[im][jn][2], acc[im][jn][3]);
        }
}

// ---------------- fused attention: LN(slots) + qproj + logits + softmax + partial updates ----------------
__global__ void k_attn(const float* __restrict__ lg, const float* __restrict__ lb,
                       float* __restrict__ attn_out) {
    int b = blockIdx.x, ch = blockIdx.y;
    int n0 = ch * 128;
    __shared__ float sn[SLOTS][DDIM];    // LN(slots)
    __shared__ float qs[SLOTS][DDIM];    // q
    __shared__ float as_[128][SLOTS];    // attn weights
    int tid = threadIdx.x, warp = tid >> 5, lane = tid & 31;

    {   // LN: warp per slot row
        int s = warp;
        const float* row = g_slots + (size_t)(b * SLOTS + s) * DDIM;
        float v[8]; float sum = 0.f, sq = 0.f;
        #pragma unroll
        for (int j = 0; j < 8; j++) {
            v[j] = row[lane + 32 * j];
            sum += v[j]; sq += v[j] * v[j];
        }
        #pragma unroll
        for (int o = 16; o; o >>= 1) {
            sum += __shfl_xor_sync(0xffffffffu, sum, o);
            sq  += __shfl_xor_sync(0xffffffffu, sq,  o);
        }
        float m = sum * (1.f / DDIM);
        float r = rsqrtf(sq * (1.f / DDIM) - m * m + LN_EPS);
        #pragma unroll
        for (int j = 0; j < 8; j++) {
            int c = lane + 32 * j;
            sn[s][c] = (v[j] - m) * r * lg[c] + lb[c];
        }
    }
    __syncthreads();

    {   // q projection: thread owns output dim d
        int d = tid;
        float accq[SLOTS];
        #pragma unroll
        for (int s = 0; s < SLOTS; s++) accq[s] = 0.f;
        #pragma unroll 8
        for (int c = 0; c < DDIM; c++) {
            float ww = g_wqT[c * DDIM + d];      // coalesced, L2-resident
            #pragma unroll
            for (int s = 0; s < SLOTS; s++) accq[s] = fmaf(sn[s][c], ww, accq[s]);
        }
        #pragma unroll
        for (int s = 0; s < SLOTS; s++) qs[s][d] = accq[s];
    }
    __syncthreads();

    for (int nn = warp; nn < 128; nn += 8) {
        int n = n0 + nn;
        const float* kr = g_k + (size_t)(b * NPOS + n) * DDIM;
        float p[SLOTS];
        #pragma unroll
        for (int s = 0; s < SLOTS; s++) p[s] = 0.f;
        #pragma unroll
        for (int j = 0; j < 8; j++) {
            int c = lane + 32 * j;
            float kv = kr[c];
            #pragma unroll
            for (int s = 0; s < SLOTS; s++) p[s] = fmaf(kv, qs[s][c], p[s]);
        }
        #pragma unroll
        for (int o = 16; o; o >>= 1)
            #pragma unroll
            for (int s = 0; s < SLOTS; s++)
                p[s] += __shfl_xor_sync(0xffffffffu, p[s], o);

        float mx = -1e30f;
        #pragma unroll
        for (int s = 0; s < SLOTS; s++) { p[s] *= ATT_SCALE; mx = fmaxf(mx, p[s]); }
        float ssum = 0.f;
        #pragma unroll
        for (int s = 0; s < SLOTS; s++) { p[s] = expf(p[s] - mx); ssum += p[s]; }
        float inv = 1.f / ssum;
        if (lane == 0) {
            #pragma unroll
            for (int s = 0; s < SLOTS; s++) {
                float a = p[s] * inv;
                as_[nn][s] = a;
                if (attn_out) attn_out[(size_t)(b * NPOS + n) * SLOTS + s] = a;
            }
        }
    }
    __syncthreads();

    int c = tid;
    float acc[SLOTS];
    #pragma unroll
    for (int s = 0; s < SLOTS; s++) acc[s] = 0.f;
    const float* vb = g_v + (size_t)(b * NPOS + n0) * DDIM + c;
    for (int nn = 0; nn < 128; nn++) {
        float vv = vb[(size_t)nn * DDIM];
        #pragma unroll
        for (int s = 0; s < SLOTS; s++) acc[s] = fmaf(as_[nn][s], vv, acc[s]);
    }
    float* up = g_upd + (size_t)((ch * BATCH + b) * SLOTS) * DDIM + c;
    #pragma unroll
    for (int s = 0; s < SLOTS; s++) up[(size_t)s * DDIM] = acc[s];
}

// ---------------- slot update: reduce partials + GRU + LN + MLP ----------------
__global__ void k_slot_update(const float* __restrict__ bih, const float* __restrict__ bhh,
                              const float* __restrict__ lg,  const float* __restrict__ lb,
                              const float* __restrict__ b1,  const float* __restrict__ b2,
                              float* __restrict__ out_slots, int write_out) {
    int b = blockIdx.x, half = blockIdx.y;
    __shared__ float u [4][DDIM];
    __shared__ float h [4][DDIM];
    __shared__ float nh[4][DDIM];
    __shared__ float hm[4][DDIM];
    int tid = threadIdx.x;
    int sbase = half * 4;

    for (int i = tid; i < 4 * DDIM; i += 256) {
        int s = i >> 8, c = i & 255;
        float a = 0.f;
        #pragma unroll
        for (int chn = 0; chn < 8; chn++)
            a += g_upd[(size_t)((chn * BATCH + b) * SLOTS + sbase + s) * DDIM + c];
        u[s][c] = a;
        h[s][c] = g_slots[(size_t)(b * SLOTS + sbase + s) * DDIM + c];
    }
    __syncthreads();

    int d = tid;
    float ir[4] = {0,0,0,0}, iz[4] = {0,0,0,0}, in_[4] = {0,0,0,0};
    float hr[4] = {0,0,0,0}, hz[4] = {0,0,0,0}, hn_[4] = {0,0,0,0};
    #pragma unroll 4
    for (int c = 0; c < DDIM; c++) {
        float a0 = g_wihT[c * 768 + d];
        float a1 = g_wihT[c * 768 + 256 + d];
        float a2 = g_wihT[c * 768 + 512 + d];
        float c0 = g_whhT[c * 768 + d];
        float c1 = g_whhT[c * 768 + 256 + d];
        float c2 = g_whhT[c * 768 + 512 + d];
        #pragma unroll
        for (int s = 0; s < 4; s++) {
            float uu = u[s][c], hh = h[s][c];
            ir[s] = fmaf(a0, uu, ir[s]); iz[s] = fmaf(a1, uu, iz[s]); in_[s] = fmaf(a2, uu, in_[s]);
            hr[s] = fmaf(c0, hh, hr[s]); hz[s] = fmaf(c1, hh, hz[s]); hn_[s] = fmaf(c2, hh, hn_[s]);
        }
    }
    float bir = bih[d], biz = bih[DDIM + d], bin = bih[2 * DDIM + d];
    float bhr = bhh[d], bhz = bhh[DDIM + d], bhn = bhh[2 * DDIM + d];
    #pragma unroll
    for (int s = 0; s < 4; s++) {
        float r = 1.f / (1.f + expf(-(ir[s] + bir + hr[s] + bhr)));
        float z = 1.f / (1.f + expf(-(iz[s] + biz + hz[s] + bhz)));
        float n = tanhf(in_[s] + bin + r * (hn_[s] + bhn));
        nh[s][d] = (1.f - z) * n + z * h[s][d];
    }
    __syncthreads();

    int warp = tid >> 5, lane = tid & 31;
    if (warp < 4) {
        int s = warp;
        float v[8]; float sum = 0.f, sq = 0.f;
        #pragma unroll
        for (int j = 0; j < 8; j++) {
            v[j] = nh[s][lane + 32 * j];
            sum += v[j]; sq += v[j] * v[j];
        }
        #pragma unroll
        for (int o = 16; o; o >>= 1) {
            sum += __shfl_xor_sync(0xffffffffu, sum, o);
            sq  += __shfl_xor_sync(0xffffffffu, sq,  o);
        }
        float m = sum * (1.f / DDIM);
        float rs = rsqrtf(sq * (1.f / DDIM) - m * m + LN_EPS);
        #pragma unroll
        for (int j = 0; j < 8; j++) {
            int c = lane + 32 * j;
            u[s][c] = (v[j] - m) * rs * lg[c] + lb[c];
        }
    }
    __syncthreads();

    float m4[4] = {0,0,0,0};
    #pragma unroll 4
    for (int c = 0; c < DDIM; c++) {
        float ww = g_w1T[c * DDIM + d];
        #pragma unroll
        for (int s = 0; s < 4; s++) m4[s] = fmaf(u[s][c], ww, m4[s]);
    }
    float bb1 = b1[d];
    #pragma unroll
    for (int s = 0; s < 4; s++) hm[s][d] = fmaxf(m4[s] + bb1, 0.f);
    __syncthreads();

    float o4[4] = {0,0,0,0};
    #pragma unroll 4
    for (int c = 0; c < DDIM; c++) {
        float ww = g_w2T[c * DDIM + d];
        #pragma unroll
        for (int s = 0; s < 4; s++) o4[s] = fmaf(hm[s][c], ww, o4[s]);
    }
    float bb2 = b2[d];
    #pragma unroll
    for (int s = 0; s < 4; s++) {
        float res = nh[s][d] + o4[s] + bb2;
        g_slots[(size_t)(b * SLOTS + sbase + s) * DDIM + d] = res;
        if (write_out && out_slots)
            out_slots[(size_t)(b * SLOTS + sbase + s) * DDIM + d] = res;
    }
}

// ---------------- host launcher ----------------
extern "C" void kernel_launch(void* const* d_in, const int* in_sizes, int n_in,
                              void* d_out, int out_size) {
    const float* x        = (const float*)d_in[0];
    const float* slots_mu = (const float*)d_in[1];
    const float* ln_in_g  = (const float*)d_in[2];
    const float* ln_in_b  = (const float*)d_in[3];
    const float* wk       = (const float*)d_in[4];
    const float* wv       = (const float*)d_in[5];
    const float* ln_s_g   = (const float*)d_in[6];
    const float* ln_s_b   = (const float*)d_in[7];
    const float* wq       = (const float*)d_in[8];
    const float* gru_wih  = (const float*)d_in[9];
    const float* gru_whh  = (const float*)d_in[10];
    const float* gru_bih  = (const float*)d_in[11];
    const float* gru_bhh  = (const float*)d_in[12];
    const float* ln_m_g   = (const float*)d_in[13];
    const float* ln_m_b   = (const float*)d_in[14];
    const float* mlp_w1   = (const float*)d_in[15];
    const float* mlp_b1   = (const float*)d_in[16];
    const float* mlp_w2   = (const float*)d_in[17];
    const float* mlp_b2   = (const float*)d_in[18];

    float* out = (float*)d_out;
    float* out_slots = nullptr;
    float* out_attn  = nullptr;
    const int SLOTS_SZ = BATCH * SLOTS * DDIM;
    const int ATTN_SZ  = BATCH * NPOS * SLOTS;
    if (out_size >= SLOTS_SZ + ATTN_SZ) { out_slots = out; out_attn = out + SLOTS_SZ; }
    else if (out_size == ATTN_SZ)       { out_attn = out; }
    else                                { out_slots = out; }

    k_prep<<<2304, 256>>>(slots_mu, wk, wv, wq, gru_wih, gru_whh, mlp_w1, mlp_w2);
    k_ln_in<<<dim3(32, 64), 256>>>(x, ln_in_g, ln_in_b);
    k_gemm_kv_mma<<<dim3(512, 4), 256>>>();

    for (int it = 0; it < NITER; it++) {
        k_attn<<<dim3(64, 8), 256>>>(ln_s_g, ln_s_b,
                                     (it == NITER - 1) ? out_attn : nullptr);
        k_slot_update<<<dim3(64, 2), 256>>>(gru_bih, gru_bhh,
                                            ln_m_g, ln_m_b, mlp_b1, mlp_b2,
                                            out_slots, (it == NITER - 1) ? 1 : 0);
    }
}